// round 5
// baseline (speedup 1.0000x reference)
#include <cuda_runtime.h>
#include <cstdint>

// Problem constants
#define S_LEN 2048
#define HDIM  4096
#define NQ    32
#define NKV   8
#define HD    128

// Scratch (static __device__ arrays: allocation-free per harness rules)
__device__ float g_q[S_LEN * NQ * HD];     // 32 MB
__device__ float g_k[S_LEN * NKV * HD];    // 8 MB
__device__ float g_v[S_LEN * NKV * HD];    // 8 MB
__device__ float g_attn[S_LEN * NQ * HD];  // 32 MB

// ---------------------------------------------------------------------------
// tf32 helpers
// ---------------------------------------------------------------------------
__device__ __forceinline__ uint32_t f32_to_tf32(float x) {
    uint32_t r;
    asm("cvt.rna.tf32.f32 %0, %1;\n" : "=r"(r) : "f"(x));
    return r;
}

__device__ __forceinline__ void mma_tf32(float* c, const uint32_t* a, const uint32_t* b) {
    asm volatile(
        "mma.sync.aligned.m16n8k8.row.col.f32.tf32.tf32.f32 "
        "{%0,%1,%2,%3}, {%4,%5,%6,%7}, {%8,%9}, {%0,%1,%2,%3};\n"
        : "+f"(c[0]), "+f"(c[1]), "+f"(c[2]), "+f"(c[3])
        : "r"(a[0]), "r"(a[1]), "r"(a[2]), "r"(a[3]), "r"(b[0]), "r"(b[1]));
}

// ---------------------------------------------------------------------------
// TF32 tensor-core GEMM: C[M,N] = A[M,K] @ B[K,N], fp32 in/out, tf32 compute.
// CTA tile 128x128x32, 256 threads (8 warps: 4 in M x 2 in N).
// blockIdx.z selects (B0,C0)/(B1,C1) so K,V projections share one launch.
// ---------------------------------------------------------------------------
#define GBK 32
#define TSTR 136

__global__ __launch_bounds__(256, 2) void tf32_gemm_kernel(
    const float* __restrict__ A,
    const float* __restrict__ B0, const float* __restrict__ B1,
    float* __restrict__ C0, float* __restrict__ C1,
    int M, int N, int K)
{
    const float* B = blockIdx.z ? B1 : B0;
    float*       C = blockIdx.z ? C1 : C0;

    __shared__ uint32_t AsT[GBK][TSTR];
    __shared__ uint32_t Bs[GBK][TSTR];

    const int tid  = threadIdx.x;
    const int lane = tid & 31;
    const int warp = tid >> 5;
    const int wm   = warp & 3;    // 0..3, 32 rows each
    const int wn   = warp >> 2;   // 0..1, 64 cols each
    const int gid  = lane >> 2;   // 0..7
    const int qid  = lane & 3;    // 0..3
    const int bx = blockIdx.x, by = blockIdx.y;

    float acc[2][8][4];
#pragma unroll
    for (int mt = 0; mt < 2; mt++)
#pragma unroll
        for (int nt = 0; nt < 8; nt++)
#pragma unroll
            for (int e = 0; e < 4; e++) acc[mt][nt][e] = 0.f;

    for (int k0 = 0; k0 < K; k0 += GBK) {
        // A tile: transposed STS [k][m]
#pragma unroll
        for (int p = 0; p < 4; p++) {
            int idx = p * 256 + tid;
            int r  = idx & 127;
            int cg = idx >> 7;
            float4 v = *(const float4*)(A + (size_t)(by * 128 + r) * K + k0 + cg * 4);
            AsT[cg * 4 + 0][r] = f32_to_tf32(v.x);
            AsT[cg * 4 + 1][r] = f32_to_tf32(v.y);
            AsT[cg * 4 + 2][r] = f32_to_tf32(v.z);
            AsT[cg * 4 + 3][r] = f32_to_tf32(v.w);
        }
        // B tile: coalesced LDG, [k][n]
#pragma unroll
        for (int p = 0; p < 4; p++) {
            int idx = p * 256 + tid;
            int r = idx >> 5;
            int c = (idx & 31) * 4;
            float4 v = *(const float4*)(B + (size_t)(k0 + r) * N + bx * 128 + c);
            Bs[r][c + 0] = f32_to_tf32(v.x);
            Bs[r][c + 1] = f32_to_tf32(v.y);
            Bs[r][c + 2] = f32_to_tf32(v.z);
            Bs[r][c + 3] = f32_to_tf32(v.w);
        }
        __syncthreads();

#pragma unroll
        for (int ks = 0; ks < 4; ks++) {
            const int kk = ks * 8;
            uint32_t af[2][4], bf[8][2];
#pragma unroll
            for (int mt = 0; mt < 2; mt++) {
                int rb = wm * 32 + mt * 16 + gid;
                af[mt][0] = AsT[kk + qid    ][rb];
                af[mt][1] = AsT[kk + qid    ][rb + 8];
                af[mt][2] = AsT[kk + qid + 4][rb];
                af[mt][3] = AsT[kk + qid + 4][rb + 8];
            }
#pragma unroll
            for (int nt = 0; nt < 8; nt++) {
                int cb = wn * 64 + nt * 8 + gid;
                bf[nt][0] = Bs[kk + qid    ][cb];
                bf[nt][1] = Bs[kk + qid + 4][cb];
            }
#pragma unroll
            for (int mt = 0; mt < 2; mt++)
#pragma unroll
                for (int nt = 0; nt < 8; nt++)
                    mma_tf32(acc[mt][nt], af[mt], bf[nt]);
        }
        __syncthreads();
    }

#pragma unroll
    for (int mt = 0; mt < 2; mt++) {
#pragma unroll
        for (int nt = 0; nt < 8; nt++) {
            int row = by * 128 + wm * 32 + mt * 16 + gid;
            int col = bx * 128 + wn * 64 + nt * 8 + qid * 2;
            *(float2*)(C + (size_t)row * N + col)       = make_float2(acc[mt][nt][0], acc[mt][nt][1]);
            *(float2*)(C + (size_t)(row + 8) * N + col) = make_float2(acc[mt][nt][2], acc[mt][nt][3]);
        }
    }
}

// ---------------------------------------------------------------------------
// RoPE (in place)
// ---------------------------------------------------------------------------
__global__ void rope_kernel(float* __restrict__ x,
                            const float* __restrict__ cosT,
                            const float* __restrict__ sinT,
                            int nh)
{
    int idx = blockIdx.x * blockDim.x + threadIdx.x;
    int total = S_LEN * nh * 64;
    if (idx >= total) return;
    int d = idx & 63;
    int h = (idx >> 6) % nh;
    int s = idx / (64 * nh);

    float* p = x + ((size_t)s * nh + h) * HD;
    float x0 = p[d];
    float x1 = p[d + 64];
    float c0 = cosT[s * HD + d],      s0 = sinT[s * HD + d];
    float c1 = cosT[s * HD + 64 + d], s1 = sinT[s * HD + 64 + d];
    p[d]      = x0 * c0 - x1 * s0;
    p[d + 64] = x1 * c1 + x0 * s1;
}

// ---------------------------------------------------------------------------
// Flash-attention with tf32 mma.sync (causal, GQA 4:1).
// 256 threads = 8 warps. Q tile 128 rows (16/warp), K/V tile 64, HD=128.
// ---------------------------------------------------------------------------
#define FQ_STR 132
#define FV_STR 136
#define FP_STR 68
#define FLASH_SMEM_BYTES ((128 * FQ_STR + 64 * FQ_STR + 64 * FV_STR + 128 * FP_STR) * 4)

__global__ __launch_bounds__(256) void flash_mma_kernel(
    const float* __restrict__ Q,
    const float* __restrict__ Kg,
    const float* __restrict__ Vg,
    float* __restrict__ O)
{
    extern __shared__ uint32_t sm[];
    uint32_t* Qs = sm;                                  // [128][132]
    uint32_t* Ks = Qs + 128 * FQ_STR;                   // [64][132]
    uint32_t* Vs = Ks + 64 * FQ_STR;                    // [64][136]
    uint32_t* Ps = Vs + 64 * FV_STR;                    // [128][68]

    const int head = blockIdx.x;          // 0..31
    const int qb   = blockIdx.y;          // 0..15
    const int hk   = head >> 2;
    const int tid  = threadIdx.x;
    const int lane = tid & 31;
    const int warp = tid >> 5;            // 0..7 (wm)
    const int gid  = lane >> 2;           // 0..7
    const int qid  = lane & 3;            // 0..3
    const int q0   = qb * 128;
    const float scale = 0.08838834764831845f;  // 1/sqrt(128)

    // Load Q tile (scale folded in, converted to tf32)
#pragma unroll
    for (int p = 0; p < 16; p++) {
        int idx = p * 256 + tid;
        int r  = idx >> 5;
        int c4 = (idx & 31) * 4;
        float4 v = *(const float4*)(Q + (size_t)(q0 + r) * (NQ * HD) + head * HD + c4);
        uint32_t* dst = Qs + r * FQ_STR + c4;
        dst[0] = f32_to_tf32(v.x * scale);
        dst[1] = f32_to_tf32(v.y * scale);
        dst[2] = f32_to_tf32(v.z * scale);
        dst[3] = f32_to_tf32(v.w * scale);
    }

    // Persistent state: rows gid (idx 0) and gid+8 (idx 1) of this warp's 16 rows
    float m_i[2] = {-1e30f, -1e30f};
    float l_i[2] = {0.f, 0.f};
    float acc2[16][4];
#pragma unroll
    for (int nt = 0; nt < 16; nt++)
#pragma unroll
        for (int e = 0; e < 4; e++) acc2[nt][e] = 0.f;

    const int row_base  = warp * 16;            // warp's first local q-row
    const int grow0     = q0 + row_base + gid;  // global q row for c0/c1
    const int nktiles   = 2 * (qb + 1);

    for (int kb = 0; kb < nktiles; kb++) {
        __syncthreads();  // prior GEMM2 Vs reads done; Qs ready on first iter
        // Load K and V tiles (64 x 128), convert to tf32
#pragma unroll
        for (int p = 0; p < 8; p++) {
            int idx = p * 256 + tid;
            int r  = idx >> 5;
            int c4 = (idx & 31) * 4;
            size_t g = (size_t)(kb * 64 + r) * (NKV * HD) + hk * HD + c4;
            float4 kv = *(const float4*)(Kg + g);
            uint32_t* kd = Ks + r * FQ_STR + c4;
            kd[0] = f32_to_tf32(kv.x); kd[1] = f32_to_tf32(kv.y);
            kd[2] = f32_to_tf32(kv.z); kd[3] = f32_to_tf32(kv.w);
            float4 vv = *(const float4*)(Vg + g);
            uint32_t* vd = Vs + r * FV_STR + c4;
            vd[0] = f32_to_tf32(vv.x); vd[1] = f32_to_tf32(vv.y);
            vd[2] = f32_to_tf32(vv.z); vd[3] = f32_to_tf32(vv.w);
        }
        __syncthreads();

        // Skip warp-tiles that are entirely above the causal diagonal
        const int kcol0 = kb * 64;
        const bool active = kcol0 <= (q0 + row_base + 15);
        if (active) {
            // GEMM1: S[16x64] = Qs(warp rows) * Ks^T
            float acc1[8][4];
#pragma unroll
            for (int nt = 0; nt < 8; nt++)
#pragma unroll
                for (int e = 0; e < 4; e++) acc1[nt][e] = 0.f;

#pragma unroll 4
            for (int ks = 0; ks < 16; ks++) {
                const int kk = ks * 8;
                uint32_t af[4];
                const uint32_t* qrow = Qs + (row_base + gid) * FQ_STR + kk;
                af[0] = qrow[qid];
                af[1] = qrow[8 * FQ_STR + qid];
                af[2] = qrow[qid + 4];
                af[3] = qrow[8 * FQ_STR + qid + 4];
#pragma unroll
                for (int nt = 0; nt < 8; nt++) {
                    uint32_t bf[2];
                    const uint32_t* krow = Ks + (nt * 8 + gid) * FQ_STR + kk;
                    bf[0] = krow[qid];
                    bf[1] = krow[qid + 4];
                    mma_tf32(acc1[nt], af, bf);
                }
            }

            // Causal mask: needed whenever ANY column in this 64-wide tile can
            // exceed the MINIMUM row this thread owns (grow0). The per-element
            // compares below handle both rows exactly.
            if (kcol0 + 63 > grow0) {
#pragma unroll
                for (int nt = 0; nt < 8; nt++) {
                    int col = kcol0 + nt * 8 + 2 * qid;
                    if (col     > grow0)     acc1[nt][0] = -1e30f;
                    if (col + 1 > grow0)     acc1[nt][1] = -1e30f;
                    if (col     > grow0 + 8) acc1[nt][2] = -1e30f;
                    if (col + 1 > grow0 + 8) acc1[nt][3] = -1e30f;
                }
            }

            // Online softmax for the two rows this thread owns
#pragma unroll
            for (int hr = 0; hr < 2; hr++) {
                const int e0 = hr * 2;
                float mx = acc1[0][e0];
#pragma unroll
                for (int nt = 0; nt < 8; nt++)
                    mx = fmaxf(mx, fmaxf(acc1[nt][e0], acc1[nt][e0 + 1]));
                mx = fmaxf(mx, __shfl_xor_sync(0xffffffffu, mx, 1));
                mx = fmaxf(mx, __shfl_xor_sync(0xffffffffu, mx, 2));
                float mnew  = fmaxf(m_i[hr], mx);
                float alpha = __expf(m_i[hr] - mnew);
                float s = 0.f;
                const int prow = row_base + gid + hr * 8;
#pragma unroll
                for (int nt = 0; nt < 8; nt++) {
                    float p0 = __expf(acc1[nt][e0]     - mnew);
                    float p1 = __expf(acc1[nt][e0 + 1] - mnew);
                    s += p0 + p1;
                    uint2 pk = make_uint2(f32_to_tf32(p0), f32_to_tf32(p1));
                    *(uint2*)(Ps + prow * FP_STR + nt * 8 + 2 * qid) = pk;
                }
                s += __shfl_xor_sync(0xffffffffu, s, 1);
                s += __shfl_xor_sync(0xffffffffu, s, 2);
                l_i[hr] = l_i[hr] * alpha + s;
                m_i[hr] = mnew;
#pragma unroll
                for (int nt = 0; nt < 16; nt++) {
                    acc2[nt][e0]     *= alpha;
                    acc2[nt][e0 + 1] *= alpha;
                }
            }
            __syncwarp();  // Ps rows are warp-private: warp-level visibility is enough

            // GEMM2: O[16x128] += P[16x64] * V[64x128]
#pragma unroll 2
            for (int ks = 0; ks < 8; ks++) {
                const int kk = ks * 8;
                uint32_t af[4];
                const uint32_t* prow = Ps + (row_base + gid) * FP_STR + kk;
                af[0] = prow[qid];
                af[1] = prow[8 * FP_STR + qid];
                af[2] = prow[qid + 4];
                af[3] = prow[8 * FP_STR + qid + 4];
#pragma unroll
                for (int nt = 0; nt < 16; nt++) {
                    uint32_t bf[2];
                    const uint32_t* vrow = Vs + (kk + qid) * FV_STR + nt * 8 + gid;
                    bf[0] = vrow[0];
                    bf[1] = vrow[4 * FV_STR];
                    mma_tf32(acc2[nt], af, bf);
                }
            }
        }
    }

    // Normalize and write out: O[q0+row][head*128 + col]
    const float inv0 = 1.f / l_i[0];
    const float inv1 = 1.f / l_i[1];
#pragma unroll
    for (int nt = 0; nt < 16; nt++) {
        int col = nt * 8 + 2 * qid;
        size_t r0off = (size_t)(grow0)     * (NQ * HD) + head * HD + col;
        size_t r1off = (size_t)(grow0 + 8) * (NQ * HD) + head * HD + col;
        *(float2*)(O + r0off) = make_float2(acc2[nt][0] * inv0, acc2[nt][1] * inv0);
        *(float2*)(O + r1off) = make_float2(acc2[nt][2] * inv1, acc2[nt][3] * inv1);
    }
}

// ---------------------------------------------------------------------------
// Host orchestration
// Inputs (metadata order): hidden_states, cos, sin, wq, wk, wv, wo
// ---------------------------------------------------------------------------
extern "C" void kernel_launch(void* const* d_in, const int* in_sizes, int n_in,
                              void* d_out, int out_size)
{
    const float* hs   = (const float*)d_in[0];
    const float* cosT = (const float*)d_in[1];
    const float* sinT = (const float*)d_in[2];
    const float* wq   = (const float*)d_in[3];
    const float* wk   = (const float*)d_in[4];
    const float* wv   = (const float*)d_in[5];
    const float* wo   = (const float*)d_in[6];
    float* out = (float*)d_out;

    float *q, *k, *v, *attn;
    cudaGetSymbolAddress((void**)&q,    g_q);
    cudaGetSymbolAddress((void**)&k,    g_k);
    cudaGetSymbolAddress((void**)&v,    g_v);
    cudaGetSymbolAddress((void**)&attn, g_attn);

    // Q projection: [2048,4096] @ [4096,4096]
    tf32_gemm_kernel<<<dim3(HDIM / 128, S_LEN / 128, 1), 256>>>(
        hs, wq, wq, q, q, S_LEN, NQ * HD, HDIM);

    // K and V projections fused via blockIdx.z: [2048,4096] @ [4096,1024]
    tf32_gemm_kernel<<<dim3((NKV * HD) / 128, S_LEN / 128, 2), 256>>>(
        hs, wk, wv, k, v, S_LEN, NKV * HD, HDIM);

    // RoPE in place
    rope_kernel<<<(S_LEN * NQ  * 64 + 255) / 256, 256>>>(q, cosT, sinT, NQ);
    rope_kernel<<<(S_LEN * NKV * 64 + 255) / 256, 256>>>(k, cosT, sinT, NKV);

    // Flash attention (tf32 mma)
    cudaFuncSetAttribute(flash_mma_kernel, cudaFuncAttributeMaxDynamicSharedMemorySize,
                         FLASH_SMEM_BYTES);
    flash_mma_kernel<<<dim3(NQ, S_LEN / 128), 256, FLASH_SMEM_BYTES>>>(q, k, v, attn);

    // Output projection: [2048,4096] @ [4096,4096] -> d_out
    tf32_gemm_kernel<<<dim3(HDIM / 128, S_LEN / 128, 1), 256>>>(
        attn, wo, wo, out, out, S_LEN, HDIM, NQ * HD);
}

// round 8
// speedup vs baseline: 1.0518x; 1.0518x over previous
#include <cuda_runtime.h>
#include <cstdint>

// Problem constants
#define S_LEN 2048
#define HDIM  4096
#define NQ    32
#define NKV   8
#define HD    128

// Scratch (static __device__ arrays: allocation-free per harness rules)
// g_q/g_k/g_v/g_attn hold tf32 bit patterns (valid fp32 values, low mantissa zero)
__device__ uint32_t g_q[S_LEN * NQ * HD];     // 32 MB
__device__ uint32_t g_k[S_LEN * NKV * HD];    // 8 MB
__device__ uint32_t g_v[S_LEN * NKV * HD];    // 8 MB
__device__ uint32_t g_attn[S_LEN * NQ * HD];  // 32 MB

// tf32 pre-converted GEMM operands
__device__ uint32_t g_hsT[S_LEN * HDIM];        // 33.5 MB
__device__ uint32_t g_wqT[HDIM * NQ * HD];      // 67 MB
__device__ uint32_t g_wkT[HDIM * NKV * HD];     // 16.8 MB
__device__ uint32_t g_wvT[HDIM * NKV * HD];     // 16.8 MB
__device__ uint32_t g_woT[NQ * HD * HDIM];      // 67 MB

// ---------------------------------------------------------------------------
// tf32 / mma / cp.async helpers
// ---------------------------------------------------------------------------
__device__ __forceinline__ uint32_t f32_to_tf32(float x) {
    uint32_t r;
    asm("cvt.rna.tf32.f32 %0, %1;\n" : "=r"(r) : "f"(x));
    return r;
}

__device__ __forceinline__ void mma_tf32(float* c, const uint32_t* a, const uint32_t* b) {
    asm volatile(
        "mma.sync.aligned.m16n8k8.row.col.f32.tf32.tf32.f32 "
        "{%0,%1,%2,%3}, {%4,%5,%6,%7}, {%8,%9}, {%0,%1,%2,%3};\n"
        : "+f"(c[0]), "+f"(c[1]), "+f"(c[2]), "+f"(c[3])
        : "r"(a[0]), "r"(a[1]), "r"(a[2]), "r"(a[3]), "r"(b[0]), "r"(b[1]));
}

__device__ __forceinline__ void cp_async16(uint32_t* dst, const uint32_t* src) {
    uint32_t s = (uint32_t)__cvta_generic_to_shared(dst);
    asm volatile("cp.async.cg.shared.global [%0], [%1], 16;\n" :: "r"(s), "l"(src));
}
__device__ __forceinline__ void cp_async_commit()  { asm volatile("cp.async.commit_group;\n"); }
__device__ __forceinline__ void cp_async_wait1()   { asm volatile("cp.async.wait_group 1;\n"); }
__device__ __forceinline__ void cp_async_wait0()   { asm volatile("cp.async.wait_group 0;\n"); }

// ---------------------------------------------------------------------------
// fp32 -> tf32 conversion pass (float4 granularity)
// ---------------------------------------------------------------------------
__global__ void cvt_tf32_kernel(const float4* __restrict__ src, uint4* __restrict__ dst, int n4) {
    int i = blockIdx.x * blockDim.x + threadIdx.x;
    if (i >= n4) return;
    float4 v = src[i];
    uint4 o;
    o.x = f32_to_tf32(v.x); o.y = f32_to_tf32(v.y);
    o.z = f32_to_tf32(v.z); o.w = f32_to_tf32(v.w);
    dst[i] = o;
}

// ---------------------------------------------------------------------------
// TF32 GEMM: C[M,N] = A[M,K] @ B[K,N].  A,B pre-converted tf32 (u32).
// CTA 128x128x32, 256 thr (8 warps: 4M x 2N), warp tile 32x64.
// cp.async double-buffered smem:
//   As [128][36]  ([m][k], stride%32==4 -> A-frag banks 4*gid+qid, CF)
//   Bs [32][136]  ([k][n], stride%32==8 -> B-frag banks 8*qid+gid, CF)
// blockIdx.z selects (B0,C0)/(B1,C1) so K,V projections share one launch.
// cvt_out: 1 -> store tf32 bit patterns (feeds downstream tf32 consumers).
// ---------------------------------------------------------------------------
#define ASTR 36
#define BSTR 136
#define A_U32 (128 * ASTR)                 // 4608
#define B_U32 (32 * BSTR)                  // 4352
#define BUF_U32 (A_U32 + B_U32)            // 8960
#define GEMM_SMEM_BYTES (2 * BUF_U32 * 4)  // 71680

static __device__ __forceinline__ void gemm_issue_tile(
    const uint32_t* __restrict__ Ag, const uint32_t* __restrict__ Bg,
    uint32_t* __restrict__ Asb, uint32_t* __restrict__ Bsb,
    int k0, int tid, int K, int N)
{
    // A tile: 128x32, [m][k] layout
#pragma unroll
    for (int p = 0; p < 4; p++) {
        int idx = p * 256 + tid;
        int r  = idx & 127;
        int cg = idx >> 7;        // 0..7 -> 4-col chunk
        cp_async16(Asb + r * ASTR + cg * 4, Ag + (size_t)r * K + k0 + cg * 4);
    }
    // B tile: 32x128, [k][n]
#pragma unroll
    for (int p = 0; p < 4; p++) {
        int idx = p * 256 + tid;
        int r = idx >> 5;
        int c = (idx & 31) * 4;
        cp_async16(Bsb + r * BSTR + c, Bg + (size_t)(k0 + r) * N + c);
    }
}

__global__ __launch_bounds__(256, 2) void tf32_gemm_db(
    const uint32_t* __restrict__ A,
    const uint32_t* __restrict__ B0, const uint32_t* __restrict__ B1,
    float* __restrict__ C0, float* __restrict__ C1,
    int M, int N, int K, int cvt_out)
{
    const uint32_t* B = blockIdx.z ? B1 : B0;
    float*          C = blockIdx.z ? C1 : C0;

    extern __shared__ uint32_t smem[];
    uint32_t* AsBuf[2] = { smem,            smem + BUF_U32 };
    uint32_t* BsBuf[2] = { smem + A_U32,    smem + BUF_U32 + A_U32 };

    const int tid  = threadIdx.x;
    const int lane = tid & 31;
    const int warp = tid >> 5;
    const int wm   = warp & 3;    // 0..3, 32 rows each
    const int wn   = warp >> 2;   // 0..1, 64 cols each
    const int gid  = lane >> 2;   // 0..7
    const int qid  = lane & 3;    // 0..3

    const uint32_t* Ag = A + (size_t)blockIdx.y * 128 * K;
    const uint32_t* Bg = B + (size_t)blockIdx.x * 128;

    float acc[2][8][4];
#pragma unroll
    for (int mt = 0; mt < 2; mt++)
#pragma unroll
        for (int nt = 0; nt < 8; nt++)
#pragma unroll
            for (int e = 0; e < 4; e++) acc[mt][nt][e] = 0.f;

    const int nt_tiles = K / 32;   // >= 2 always here

    // Prologue: fill both buffers
    gemm_issue_tile(Ag, Bg, AsBuf[0], BsBuf[0], 0, tid, K, N);
    cp_async_commit();
    gemm_issue_tile(Ag, Bg, AsBuf[1], BsBuf[1], 32, tid, K, N);
    cp_async_commit();

    for (int t = 0; t < nt_tiles; t++) {
        if (t < nt_tiles - 1) cp_async_wait1(); else cp_async_wait0();
        __syncthreads();   // tile t visible to all warps

        const uint32_t* As = AsBuf[t & 1];
        const uint32_t* Bs = BsBuf[t & 1];
#pragma unroll
        for (int ks = 0; ks < 4; ks++) {
            const int kk = ks * 8;
            uint32_t af[2][4], bf[8][2];
#pragma unroll
            for (int mt = 0; mt < 2; mt++) {
                int rb = wm * 32 + mt * 16 + gid;
                af[mt][0] = As[(rb)     * ASTR + kk + qid];
                af[mt][1] = As[(rb + 8) * ASTR + kk + qid];
                af[mt][2] = As[(rb)     * ASTR + kk + qid + 4];
                af[mt][3] = As[(rb + 8) * ASTR + kk + qid + 4];
            }
#pragma unroll
            for (int nt = 0; nt < 8; nt++) {
                int cb = wn * 64 + nt * 8 + gid;
                bf[nt][0] = Bs[(kk + qid)     * BSTR + cb];
                bf[nt][1] = Bs[(kk + qid + 4) * BSTR + cb];
            }
#pragma unroll
            for (int mt = 0; mt < 2; mt++)
#pragma unroll
                for (int nt = 0; nt < 8; nt++)
                    mma_tf32(acc[mt][nt], af[mt], bf[nt]);
        }
        __syncthreads();   // all warps done reading buffer t&1

        if (t + 2 < nt_tiles) {
            gemm_issue_tile(Ag, Bg, AsBuf[t & 1], BsBuf[t & 1], (t + 2) * 32, tid, K, N);
            cp_async_commit();
        }
    }

    // Epilogue (optionally emit tf32 bit patterns)
#pragma unroll
    for (int mt = 0; mt < 2; mt++) {
#pragma unroll
        for (int nt = 0; nt < 8; nt++) {
            int row = blockIdx.y * 128 + wm * 32 + mt * 16 + gid;
            int col = blockIdx.x * 128 + wn * 64 + nt * 8 + qid * 2;
            float o0 = acc[mt][nt][0], o1 = acc[mt][nt][1];
            float o2 = acc[mt][nt][2], o3 = acc[mt][nt][3];
            if (cvt_out) {
                o0 = __uint_as_float(f32_to_tf32(o0));
                o1 = __uint_as_float(f32_to_tf32(o1));
                o2 = __uint_as_float(f32_to_tf32(o2));
                o3 = __uint_as_float(f32_to_tf32(o3));
            }
            *(float2*)(C + (size_t)row * N + col)       = make_float2(o0, o1);
            *(float2*)(C + (size_t)(row + 8) * N + col) = make_float2(o2, o3);
        }
    }
}

// ---------------------------------------------------------------------------
// RoPE (in place, u32 tf32-bits in -> tf32-bits out, optional folded scale)
// ---------------------------------------------------------------------------
__global__ void rope_tf32_kernel(uint32_t* __restrict__ x,
                                 const float* __restrict__ cosT,
                                 const float* __restrict__ sinT,
                                 int nh, float scale)
{
    int idx = blockIdx.x * blockDim.x + threadIdx.x;
    int total = S_LEN * nh * 64;
    if (idx >= total) return;
    int d = idx & 63;
    int h = (idx >> 6) % nh;
    int s = idx / (64 * nh);

    uint32_t* p = x + ((size_t)s * nh + h) * HD;
    float x0 = __uint_as_float(p[d]);
    float x1 = __uint_as_float(p[d + 64]);
    float c0 = cosT[s * HD + d],      s0 = sinT[s * HD + d];
    float c1 = cosT[s * HD + 64 + d], s1 = sinT[s * HD + 64 + d];
    p[d]      = f32_to_tf32((x0 * c0 - x1 * s0) * scale);
    p[d + 64] = f32_to_tf32((x1 * c1 + x0 * s1) * scale);
}

// ---------------------------------------------------------------------------
// Flash-attention with tf32 mma.sync (causal, GQA 4:1).
// 256 threads = 8 warps. Q tile 128 rows (16/warp), K/V tile 64, HD=128.
// All inputs are pre-converted tf32 bits (Q pre-scaled): load path is pure
// copy (uint4 for Q, cp.async for K/V) -- no cvt in the loop.
// ---------------------------------------------------------------------------
#define FQ_STR 132
#define FV_STR 136
#define FP_STR 68
#define FLASH_SMEM_BYTES ((128 * FQ_STR + 64 * FQ_STR + 64 * FV_STR + 128 * FP_STR) * 4)

__global__ __launch_bounds__(256) void flash_mma_kernel(
    const uint32_t* __restrict__ Q,
    const uint32_t* __restrict__ Kg,
    const uint32_t* __restrict__ Vg,
    uint32_t* __restrict__ O)   // tf32 bits out
{
    extern __shared__ uint32_t sm[];
    uint32_t* Qs = sm;                                  // [128][132]
    uint32_t* Ks = Qs + 128 * FQ_STR;                   // [64][132]
    uint32_t* Vs = Ks + 64 * FQ_STR;                    // [64][136]
    uint32_t* Ps = Vs + 64 * FV_STR;                    // [128][68]

    const int head = blockIdx.x;          // 0..31
    const int qb   = blockIdx.y;          // 0..15
    const int hk   = head >> 2;
    const int tid  = threadIdx.x;
    const int lane = tid & 31;
    const int warp = tid >> 5;            // 0..7 (wm)
    const int gid  = lane >> 2;           // 0..7
    const int qid  = lane & 3;            // 0..3
    const int q0   = qb * 128;

    // Load Q tile (already tf32 bits, scale folded in by rope)
#pragma unroll
    for (int p = 0; p < 16; p++) {
        int idx = p * 256 + tid;
        int r  = idx >> 5;
        int c4 = (idx & 31) * 4;
        uint4 v = *(const uint4*)(Q + (size_t)(q0 + r) * (NQ * HD) + head * HD + c4);
        *(uint4*)(Qs + r * FQ_STR + c4) = v;
    }

    float m_i[2] = {-1e30f, -1e30f};
    float l_i[2] = {0.f, 0.f};
    float acc2[16][4];
#pragma unroll
    for (int nt = 0; nt < 16; nt++)
#pragma unroll
        for (int e = 0; e < 4; e++) acc2[nt][e] = 0.f;

    const int row_base  = warp * 16;
    const int grow0     = q0 + row_base + gid;
    const int nktiles   = 2 * (qb + 1);

    for (int kb = 0; kb < nktiles; kb++) {
        __syncthreads();  // prior GEMM2 Vs reads done; Qs ready on first iter
        // Load K and V tiles (64 x 128) via cp.async, no conversion needed
#pragma unroll
        for (int p = 0; p < 8; p++) {
            int idx = p * 256 + tid;
            int r  = idx >> 5;
            int c4 = (idx & 31) * 4;
            size_t g = (size_t)(kb * 64 + r) * (NKV * HD) + hk * HD + c4;
            cp_async16(Ks + r * FQ_STR + c4, Kg + g);
            cp_async16(Vs + r * FV_STR + c4, Vg + g);
        }
        cp_async_commit();
        cp_async_wait0();
        __syncthreads();

        const int kcol0 = kb * 64;
        const bool active = kcol0 <= (q0 + row_base + 15);
        if (active) {
            float acc1[8][4];
#pragma unroll
            for (int nt = 0; nt < 8; nt++)
#pragma unroll
                for (int e = 0; e < 4; e++) acc1[nt][e] = 0.f;

#pragma unroll 4
            for (int ks = 0; ks < 16; ks++) {
                const int kk = ks * 8;
                uint32_t af[4];
                const uint32_t* qrow = Qs + (row_base + gid) * FQ_STR + kk;
                af[0] = qrow[qid];
                af[1] = qrow[8 * FQ_STR + qid];
                af[2] = qrow[qid + 4];
                af[3] = qrow[8 * FQ_STR + qid + 4];
#pragma unroll
                for (int nt = 0; nt < 8; nt++) {
                    uint32_t bf[2];
                    const uint32_t* krow = Ks + (nt * 8 + gid) * FQ_STR + kk;
                    bf[0] = krow[qid];
                    bf[1] = krow[qid + 4];
                    mma_tf32(acc1[nt], af, bf);
                }
            }

            // Causal mask vs the MINIMUM row this thread owns
            if (kcol0 + 63 > grow0) {
#pragma unroll
                for (int nt = 0; nt < 8; nt++) {
                    int col = kcol0 + nt * 8 + 2 * qid;
                    if (col     > grow0)     acc1[nt][0] = -1e30f;
                    if (col + 1 > grow0)     acc1[nt][1] = -1e30f;
                    if (col     > grow0 + 8) acc1[nt][2] = -1e30f;
                    if (col + 1 > grow0 + 8) acc1[nt][3] = -1e30f;
                }
            }

            // Online softmax
#pragma unroll
            for (int hr = 0; hr < 2; hr++) {
                const int e0 = hr * 2;
                float mx = acc1[0][e0];
#pragma unroll
                for (int nt = 0; nt < 8; nt++)
                    mx = fmaxf(mx, fmaxf(acc1[nt][e0], acc1[nt][e0 + 1]));
                mx = fmaxf(mx, __shfl_xor_sync(0xffffffffu, mx, 1));
                mx = fmaxf(mx, __shfl_xor_sync(0xffffffffu, mx, 2));
                float mnew  = fmaxf(m_i[hr], mx);
                float alpha = __expf(m_i[hr] - mnew);
                float s = 0.f;
                const int prow = row_base + gid + hr * 8;
#pragma unroll
                for (int nt = 0; nt < 8; nt++) {
                    float p0 = __expf(acc1[nt][e0]     - mnew);
                    float p1 = __expf(acc1[nt][e0 + 1] - mnew);
                    s += p0 + p1;
                    uint2 pk = make_uint2(f32_to_tf32(p0), f32_to_tf32(p1));
                    *(uint2*)(Ps + prow * FP_STR + nt * 8 + 2 * qid) = pk;
                }
                s += __shfl_xor_sync(0xffffffffu, s, 1);
                s += __shfl_xor_sync(0xffffffffu, s, 2);
                l_i[hr] = l_i[hr] * alpha + s;
                m_i[hr] = mnew;
#pragma unroll
                for (int nt = 0; nt < 16; nt++) {
                    acc2[nt][e0]     *= alpha;
                    acc2[nt][e0 + 1] *= alpha;
                }
            }
            __syncwarp();

            // GEMM2: O += P * V
#pragma unroll 2
            for (int ks = 0; ks < 8; ks++) {
                const int kk = ks * 8;
                uint32_t af[4];
                const uint32_t* prow = Ps + (row_base + gid) * FP_STR + kk;
                af[0] = prow[qid];
                af[1] = prow[8 * FP_STR + qid];
                af[2] = prow[qid + 4];
                af[3] = prow[8 * FP_STR + qid + 4];
#pragma unroll
                for (int nt = 0; nt < 16; nt++) {
                    uint32_t bf[2];
                    const uint32_t* vrow = Vs + (kk + qid) * FV_STR + nt * 8 + gid;
                    bf[0] = vrow[0];
                    bf[1] = vrow[4 * FV_STR];
                    mma_tf32(acc2[nt], af, bf);
                }
            }
        }
    }

    // Normalize and write out as tf32 bits
    const float inv0 = 1.f / l_i[0];
    const float inv1 = 1.f / l_i[1];
#pragma unroll
    for (int nt = 0; nt < 16; nt++) {
        int col = nt * 8 + 2 * qid;
        size_t r0off = (size_t)(grow0)     * (NQ * HD) + head * HD + col;
        size_t r1off = (size_t)(grow0 + 8) * (NQ * HD) + head * HD + col;
        *(uint2*)(O + r0off) = make_uint2(f32_to_tf32(acc2[nt][0] * inv0),
                                          f32_to_tf32(acc2[nt][1] * inv0));
        *(uint2*)(O + r1off) = make_uint2(f32_to_tf32(acc2[nt][2] * inv1),
                                          f32_to_tf32(acc2[nt][3] * inv1));
    }
}

// ---------------------------------------------------------------------------
// Host orchestration
// Inputs (metadata order): hidden_states, cos, sin, wq, wk, wv, wo
// ---------------------------------------------------------------------------
extern "C" void kernel_launch(void* const* d_in, const int* in_sizes, int n_in,
                              void* d_out, int out_size)
{
    const float* hs   = (const float*)d_in[0];
    const float* cosT = (const float*)d_in[1];
    const float* sinT = (const float*)d_in[2];
    const float* wq   = (const float*)d_in[3];
    const float* wk   = (const float*)d_in[4];
    const float* wv   = (const float*)d_in[5];
    const float* wo   = (const float*)d_in[6];
    float* out = (float*)d_out;

    uint32_t *q, *k, *v, *attn;
    uint32_t *hsT, *wqT, *wkT, *wvT, *woT;
    cudaGetSymbolAddress((void**)&q,    g_q);
    cudaGetSymbolAddress((void**)&k,    g_k);
    cudaGetSymbolAddress((void**)&v,    g_v);
    cudaGetSymbolAddress((void**)&attn, g_attn);
    cudaGetSymbolAddress((void**)&hsT,  g_hsT);
    cudaGetSymbolAddress((void**)&wqT,  g_wqT);
    cudaGetSymbolAddress((void**)&wkT,  g_wkT);
    cudaGetSymbolAddress((void**)&wvT,  g_wvT);
    cudaGetSymbolAddress((void**)&woT,  g_woT);

    cudaFuncSetAttribute(tf32_gemm_db, cudaFuncAttributeMaxDynamicSharedMemorySize,
                         GEMM_SMEM_BYTES);
    cudaFuncSetAttribute(flash_mma_kernel, cudaFuncAttributeMaxDynamicSharedMemorySize,
                         FLASH_SMEM_BYTES);

    // Pre-convert fp32 -> tf32
    {
        const int T = 256;
        int n;
        n = S_LEN * HDIM / 4;
        cvt_tf32_kernel<<<(n + T - 1) / T, T>>>((const float4*)hs, (uint4*)hsT, n);
        n = HDIM * NQ * HD / 4;
        cvt_tf32_kernel<<<(n + T - 1) / T, T>>>((const float4*)wq, (uint4*)wqT, n);
        n = HDIM * NKV * HD / 4;
        cvt_tf32_kernel<<<(n + T - 1) / T, T>>>((const float4*)wk, (uint4*)wkT, n);
        cvt_tf32_kernel<<<(n + T - 1) / T, T>>>((const float4*)wv, (uint4*)wvT, n);
        n = NQ * HD * HDIM / 4;
        cvt_tf32_kernel<<<(n + T - 1) / T, T>>>((const float4*)wo, (uint4*)woT, n);
    }

    // Q projection (tf32-bit output): [2048,4096] @ [4096,4096]
    tf32_gemm_db<<<dim3(HDIM / 128, S_LEN / 128, 1), 256, GEMM_SMEM_BYTES>>>(
        hsT, wqT, wqT, (float*)q, (float*)q, S_LEN, NQ * HD, HDIM, 1);

    // K and V projections (tf32-bit output), fused via blockIdx.z
    tf32_gemm_db<<<dim3((NKV * HD) / 128, S_LEN / 128, 2), 256, GEMM_SMEM_BYTES>>>(
        hsT, wkT, wvT, (float*)k, (float*)v, S_LEN, NKV * HD, HDIM, 1);

    // RoPE in place (tf32 bits in/out); attention scale folded into Q
    rope_tf32_kernel<<<(S_LEN * NQ  * 64 + 255) / 256, 256>>>(
        q, cosT, sinT, NQ, 0.08838834764831845f);
    rope_tf32_kernel<<<(S_LEN * NKV * 64 + 255) / 256, 256>>>(
        k, cosT, sinT, NKV, 1.0f);

    // Flash attention (tf32 mma) -> attn holds tf32 bits
    flash_mma_kernel<<<dim3(NQ, S_LEN / 128), 256, FLASH_SMEM_BYTES>>>(
        q, k, v, attn);

    // Output projection: [2048,4096] @ [4096,4096] -> d_out (fp32)
    tf32_gemm_db<<<dim3(HDIM / 128, S_LEN / 128, 1), 256, GEMM_SMEM_BYTES>>>(
        attn, woT, woT, out, out, S_LEN, HDIM, NQ * HD, 0);
}

// round 17
// speedup vs baseline: 1.1074x; 1.0529x over previous
#include <cuda_runtime.h>
#include <cstdint>

// Problem constants
#define S_LEN 2048
#define HDIM  4096
#define NQ    32
#define NKV   8
#define HD    128

// Scratch (static __device__ arrays: allocation-free per harness rules)
// g_q/g_k/g_v/g_attn hold tf32 bit patterns (valid fp32 values, low mantissa zero)
__device__ uint32_t g_q[S_LEN * NQ * HD];     // 32 MB
__device__ uint32_t g_k[S_LEN * NKV * HD];    // 8 MB
__device__ uint32_t g_v[S_LEN * NKV * HD];    // 8 MB
__device__ uint32_t g_attn[S_LEN * NQ * HD];  // 32 MB

// tf32 pre-converted GEMM operands (row-major, same layout as inputs)
__device__ uint32_t g_hsT[S_LEN * HDIM];
__device__ uint32_t g_wqT[HDIM * NQ * HD];
__device__ uint32_t g_wkT[HDIM * NKV * HD];
__device__ uint32_t g_wvT[HDIM * NKV * HD];
__device__ uint32_t g_woT[NQ * HD * HDIM];

// ---------------------------------------------------------------------------
// helpers
// ---------------------------------------------------------------------------
__device__ __forceinline__ uint32_t f32_to_tf32(float x) {
    uint32_t r;
    asm("cvt.rna.tf32.f32 %0, %1;\n" : "=r"(r) : "f"(x));
    return r;
}

__device__ __forceinline__ void mma_tf32(float* c, const uint32_t* a, const uint32_t* b) {
    asm volatile(
        "mma.sync.aligned.m16n8k8.row.col.f32.tf32.tf32.f32 "
        "{%0,%1,%2,%3}, {%4,%5,%6,%7}, {%8,%9}, {%0,%1,%2,%3};\n"
        : "+f"(c[0]), "+f"(c[1]), "+f"(c[2]), "+f"(c[3])
        : "r"(a[0]), "r"(a[1]), "r"(a[2]), "r"(a[3]), "r"(b[0]), "r"(b[1]));
}

__device__ __forceinline__ void cp_async16(uint32_t* dst, const uint32_t* src) {
    uint32_t s = (uint32_t)__cvta_generic_to_shared(dst);
    asm volatile("cp.async.cg.shared.global [%0], [%1], 16;\n" :: "r"(s), "l"(src));
}
__device__ __forceinline__ void cp_async_commit() { asm volatile("cp.async.commit_group;\n"); }
__device__ __forceinline__ void cp_async_wait1()  { asm volatile("cp.async.wait_group 1;\n"); }
__device__ __forceinline__ void cp_async_wait0()  { asm volatile("cp.async.wait_group 0;\n"); }

// ---------------------------------------------------------------------------
// fp32 -> tf32 conversion pass (float4 granularity)
// ---------------------------------------------------------------------------
__global__ void cvt_tf32_kernel(const float4* __restrict__ src, uint4* __restrict__ dst, int n4) {
    int i = blockIdx.x * blockDim.x + threadIdx.x;
    if (i >= n4) return;
    float4 v = src[i];
    uint4 o;
    o.x = f32_to_tf32(v.x); o.y = f32_to_tf32(v.y);
    o.z = f32_to_tf32(v.z); o.w = f32_to_tf32(v.w);
    dst[i] = o;
}

// ---------------------------------------------------------------------------
// TF32 GEMM (legacy mma.sync): C[M,N] = A[M,K] @ B[K,N], tf32 u32 in, fp32 out.
// CTA 128x128x32, 256 thr (8 warps: 4M x 2N), warp tile 32x64.
// 3-buffer / 2-deep cp.async ring, ONE __syncthreads per k-tile:
//   at iter t: wait tile t -> sync (all reads of buf[(t-1)%3] done)
//   -> issue tile t+2 into buf[(t+2)%3] == buf[(t-1)%3]  (safe, overlaps compute)
//   -> compute from buf[t%3].
// Smem layouts (both conflict-free for fragment LDS):
//   As [128][36]  ([m][k]); Bs [32][136]  ([k][n]).
// blockIdx.z selects (B0,C0)/(B1,C1).  cvt_out: emit tf32 bit patterns.
// ---------------------------------------------------------------------------
#define ASTR 36
#define BSTR 136
#define A_U32 (128 * ASTR)                      // 4608
#define B_U32 (32 * BSTR)                       // 4352
#define BUF_U32 (A_U32 + B_U32)                 // 8960
#define GEMM_NSTAGE 3
#define GEMM_SMEM_BYTES (GEMM_NSTAGE * BUF_U32 * 4)   // 107520 -> 2 CTAs/SM

static __device__ __forceinline__ void gemm_issue_tile(
    const uint32_t* __restrict__ Ag, const uint32_t* __restrict__ Bg,
    uint32_t* __restrict__ buf, int k0, int tid, int K, int N)
{
    uint32_t* Asb = buf;
    uint32_t* Bsb = buf + A_U32;
    // A tile: 128x32, [m][k]
#pragma unroll
    for (int p = 0; p < 4; p++) {
        int idx = p * 256 + tid;
        int r  = idx & 127;
        int cg = idx >> 7;
        cp_async16(Asb + r * ASTR + cg * 4, Ag + (size_t)r * K + k0 + cg * 4);
    }
    // B tile: 32x128, [k][n]
#pragma unroll
    for (int p = 0; p < 4; p++) {
        int idx = p * 256 + tid;
        int r = idx >> 5;
        int c = (idx & 31) * 4;
        cp_async16(Bsb + r * BSTR + c, Bg + (size_t)(k0 + r) * N + c);
    }
}

__global__ __launch_bounds__(256, 2) void tf32_gemm_db(
    const uint32_t* __restrict__ A,
    const uint32_t* __restrict__ B0, const uint32_t* __restrict__ B1,
    float* __restrict__ C0, float* __restrict__ C1,
    int M, int N, int K, int cvt_out)
{
    const uint32_t* B = blockIdx.z ? B1 : B0;
    float*          C = blockIdx.z ? C1 : C0;

    extern __shared__ uint32_t smem[];

    const int tid  = threadIdx.x;
    const int lane = tid & 31;
    const int warp = tid >> 5;
    const int wm   = warp & 3;    // 0..3, 32 rows each
    const int wn   = warp >> 2;   // 0..1, 64 cols each
    const int gid  = lane >> 2;   // 0..7
    const int qid  = lane & 3;    // 0..3

    const uint32_t* Ag = A + (size_t)blockIdx.y * 128 * K;
    const uint32_t* Bg = B + (size_t)blockIdx.x * 128;

    float acc[2][8][4];
#pragma unroll
    for (int mt = 0; mt < 2; mt++)
#pragma unroll
        for (int nt = 0; nt < 8; nt++)
#pragma unroll
            for (int e = 0; e < 4; e++) acc[mt][nt][e] = 0.f;

    const int nt_tiles = K / 32;   // 128 (K=4096) or 32 (K=1024); >= 2

    // Prologue: 2 tiles in flight
    gemm_issue_tile(Ag, Bg, smem, 0, tid, K, N);
    cp_async_commit();
    gemm_issue_tile(Ag, Bg, smem + BUF_U32, 32, tid, K, N);
    cp_async_commit();

    for (int t = 0; t < nt_tiles; t++) {
        if (t < nt_tiles - 1) cp_async_wait1(); else cp_async_wait0();
        __syncthreads();   // tile t landed; all reads of buf[(t-1)%3] finished

        // Refill the buffer freed last iteration, before computing (overlap)
        if (t + 2 < nt_tiles) {
            gemm_issue_tile(Ag, Bg, smem + ((t + 2) % GEMM_NSTAGE) * BUF_U32,
                            (t + 2) * 32, tid, K, N);
            cp_async_commit();
        }

        const uint32_t* As = smem + (t % GEMM_NSTAGE) * BUF_U32;
        const uint32_t* Bs = As + A_U32;
#pragma unroll
        for (int ks = 0; ks < 4; ks++) {
            const int kk = ks * 8;
            uint32_t af[2][4], bf[8][2];
#pragma unroll
            for (int mt = 0; mt < 2; mt++) {
                int rb = wm * 32 + mt * 16 + gid;
                af[mt][0] = As[(rb)     * ASTR + kk + qid];
                af[mt][1] = As[(rb + 8) * ASTR + kk + qid];
                af[mt][2] = As[(rb)     * ASTR + kk + qid + 4];
                af[mt][3] = As[(rb + 8) * ASTR + kk + qid + 4];
            }
#pragma unroll
            for (int nt = 0; nt < 8; nt++) {
                int cb = wn * 64 + nt * 8 + gid;
                bf[nt][0] = Bs[(kk + qid)     * BSTR + cb];
                bf[nt][1] = Bs[(kk + qid + 4) * BSTR + cb];
            }
#pragma unroll
            for (int mt = 0; mt < 2; mt++)
#pragma unroll
                for (int nt = 0; nt < 8; nt++)
                    mma_tf32(acc[mt][nt], af[mt], bf[nt]);
        }
    }

    // Epilogue (optionally emit tf32 bit patterns)
#pragma unroll
    for (int mt = 0; mt < 2; mt++) {
#pragma unroll
        for (int nt = 0; nt < 8; nt++) {
            int row = blockIdx.y * 128 + wm * 32 + mt * 16 + gid;
            int col = blockIdx.x * 128 + wn * 64 + nt * 8 + qid * 2;
            float o0 = acc[mt][nt][0], o1 = acc[mt][nt][1];
            float o2 = acc[mt][nt][2], o3 = acc[mt][nt][3];
            if (cvt_out) {
                o0 = __uint_as_float(f32_to_tf32(o0));
                o1 = __uint_as_float(f32_to_tf32(o1));
                o2 = __uint_as_float(f32_to_tf32(o2));
                o3 = __uint_as_float(f32_to_tf32(o3));
            }
            *(float2*)(C + (size_t)row * N + col)       = make_float2(o0, o1);
            *(float2*)(C + (size_t)(row + 8) * N + col) = make_float2(o2, o3);
        }
    }
}

// ---------------------------------------------------------------------------
// RoPE (in place, u32 tf32-bits in -> tf32-bits out, optional folded scale)
// ---------------------------------------------------------------------------
__global__ void rope_tf32_kernel(uint32_t* __restrict__ x,
                                 const float* __restrict__ cosT,
                                 const float* __restrict__ sinT,
                                 int nh, float scale)
{
    int idx = blockIdx.x * blockDim.x + threadIdx.x;
    int total = S_LEN * nh * 64;
    if (idx >= total) return;
    int d = idx & 63;
    int h = (idx >> 6) % nh;
    int s = idx / (64 * nh);

    uint32_t* p = x + ((size_t)s * nh + h) * HD;
    float x0 = __uint_as_float(p[d]);
    float x1 = __uint_as_float(p[d + 64]);
    float c0 = cosT[s * HD + d],      s0 = sinT[s * HD + d];
    float c1 = cosT[s * HD + 64 + d], s1 = sinT[s * HD + 64 + d];
    p[d]      = f32_to_tf32((x0 * c0 - x1 * s0) * scale);
    p[d + 64] = f32_to_tf32((x1 * c1 + x0 * s1) * scale);
}

// ---------------------------------------------------------------------------
// Flash-attention with tf32 mma.sync (causal, GQA 4:1) -- UNCHANGED (passing)
// ---------------------------------------------------------------------------
#define FQ_STR 132
#define FV_STR 136
#define FP_STR 68
#define FLASH_SMEM_BYTES ((128 * FQ_STR + 64 * FQ_STR + 64 * FV_STR + 128 * FP_STR) * 4)

__global__ __launch_bounds__(256) void flash_mma_kernel(
    const uint32_t* __restrict__ Q,
    const uint32_t* __restrict__ Kg,
    const uint32_t* __restrict__ Vg,
    uint32_t* __restrict__ O)
{
    extern __shared__ uint32_t sm[];
    uint32_t* Qs = sm;
    uint32_t* Ks = Qs + 128 * FQ_STR;
    uint32_t* Vs = Ks + 64 * FQ_STR;
    uint32_t* Ps = Vs + 64 * FV_STR;

    const int head = blockIdx.x;
    const int qb   = blockIdx.y;
    const int hk   = head >> 2;
    const int tid  = threadIdx.x;
    const int lane = tid & 31;
    const int warp = tid >> 5;
    const int gid  = lane >> 2;
    const int qid  = lane & 3;
    const int q0   = qb * 128;

#pragma unroll
    for (int p = 0; p < 16; p++) {
        int idx = p * 256 + tid;
        int r  = idx >> 5;
        int c4 = (idx & 31) * 4;
        uint4 v = *(const uint4*)(Q + (size_t)(q0 + r) * (NQ * HD) + head * HD + c4);
        *(uint4*)(Qs + r * FQ_STR + c4) = v;
    }

    float m_i[2] = {-1e30f, -1e30f};
    float l_i[2] = {0.f, 0.f};
    float acc2[16][4];
#pragma unroll
    for (int nt = 0; nt < 16; nt++)
#pragma unroll
        for (int e = 0; e < 4; e++) acc2[nt][e] = 0.f;

    const int row_base = warp * 16;
    const int grow0    = q0 + row_base + gid;
    const int nktiles  = 2 * (qb + 1);

    for (int kb = 0; kb < nktiles; kb++) {
        __syncthreads();
#pragma unroll
        for (int p = 0; p < 8; p++) {
            int idx = p * 256 + tid;
            int r  = idx >> 5;
            int c4 = (idx & 31) * 4;
            size_t g = (size_t)(kb * 64 + r) * (NKV * HD) + hk * HD + c4;
            cp_async16(Ks + r * FQ_STR + c4, Kg + g);
            cp_async16(Vs + r * FV_STR + c4, Vg + g);
        }
        cp_async_commit();
        cp_async_wait0();
        __syncthreads();

        const int kcol0 = kb * 64;
        const bool active = kcol0 <= (q0 + row_base + 15);
        if (active) {
            float acc1[8][4];
#pragma unroll
            for (int nt = 0; nt < 8; nt++)
#pragma unroll
                for (int e = 0; e < 4; e++) acc1[nt][e] = 0.f;

#pragma unroll 4
            for (int ks = 0; ks < 16; ks++) {
                const int kk = ks * 8;
                uint32_t af[4];
                const uint32_t* qrow = Qs + (row_base + gid) * FQ_STR + kk;
                af[0] = qrow[qid];
                af[1] = qrow[8 * FQ_STR + qid];
                af[2] = qrow[qid + 4];
                af[3] = qrow[8 * FQ_STR + qid + 4];
#pragma unroll
                for (int nt = 0; nt < 8; nt++) {
                    uint32_t bf[2];
                    const uint32_t* krow = Ks + (nt * 8 + gid) * FQ_STR + kk;
                    bf[0] = krow[qid];
                    bf[1] = krow[qid + 4];
                    mma_tf32(acc1[nt], af, bf);
                }
            }

            if (kcol0 + 63 > grow0) {
#pragma unroll
                for (int nt = 0; nt < 8; nt++) {
                    int col = kcol0 + nt * 8 + 2 * qid;
                    if (col     > grow0)     acc1[nt][0] = -1e30f;
                    if (col + 1 > grow0)     acc1[nt][1] = -1e30f;
                    if (col     > grow0 + 8) acc1[nt][2] = -1e30f;
                    if (col + 1 > grow0 + 8) acc1[nt][3] = -1e30f;
                }
            }

#pragma unroll
            for (int hr = 0; hr < 2; hr++) {
                const int e0 = hr * 2;
                float mx = acc1[0][e0];
#pragma unroll
                for (int nt = 0; nt < 8; nt++)
                    mx = fmaxf(mx, fmaxf(acc1[nt][e0], acc1[nt][e0 + 1]));
                mx = fmaxf(mx, __shfl_xor_sync(0xffffffffu, mx, 1));
                mx = fmaxf(mx, __shfl_xor_sync(0xffffffffu, mx, 2));
                float mnew  = fmaxf(m_i[hr], mx);
                float alpha = __expf(m_i[hr] - mnew);
                float s = 0.f;
                const int prow = row_base + gid + hr * 8;
#pragma unroll
                for (int nt = 0; nt < 8; nt++) {
                    float p0 = __expf(acc1[nt][e0]     - mnew);
                    float p1 = __expf(acc1[nt][e0 + 1] - mnew);
                    s += p0 + p1;
                    uint2 pk = make_uint2(f32_to_tf32(p0), f32_to_tf32(p1));
                    *(uint2*)(Ps + prow * FP_STR + nt * 8 + 2 * qid) = pk;
                }
                s += __shfl_xor_sync(0xffffffffu, s, 1);
                s += __shfl_xor_sync(0xffffffffu, s, 2);
                l_i[hr] = l_i[hr] * alpha + s;
                m_i[hr] = mnew;
#pragma unroll
                for (int nt = 0; nt < 16; nt++) {
                    acc2[nt][e0]     *= alpha;
                    acc2[nt][e0 + 1] *= alpha;
                }
            }
            __syncwarp();

#pragma unroll 2
            for (int ks = 0; ks < 8; ks++) {
                const int kk = ks * 8;
                uint32_t af[4];
                const uint32_t* prow = Ps + (row_base + gid) * FP_STR + kk;
                af[0] = prow[qid];
                af[1] = prow[8 * FP_STR + qid];
                af[2] = prow[qid + 4];
                af[3] = prow[8 * FP_STR + qid + 4];
#pragma unroll
                for (int nt = 0; nt < 16; nt++) {
                    uint32_t bf[2];
                    const uint32_t* vrow = Vs + (kk + qid) * FV_STR + nt * 8 + gid;
                    bf[0] = vrow[0];
                    bf[1] = vrow[4 * FV_STR];
                    mma_tf32(acc2[nt], af, bf);
                }
            }
        }
    }

    const float inv0 = 1.f / l_i[0];
    const float inv1 = 1.f / l_i[1];
#pragma unroll
    for (int nt = 0; nt < 16; nt++) {
        int col = nt * 8 + 2 * qid;
        size_t r0off = (size_t)(grow0)     * (NQ * HD) + head * HD + col;
        size_t r1off = (size_t)(grow0 + 8) * (NQ * HD) + head * HD + col;
        *(uint2*)(O + r0off) = make_uint2(f32_to_tf32(acc2[nt][0] * inv0),
                                          f32_to_tf32(acc2[nt][1] * inv0));
        *(uint2*)(O + r1off) = make_uint2(f32_to_tf32(acc2[nt][2] * inv1),
                                          f32_to_tf32(acc2[nt][3] * inv1));
    }
}

// ---------------------------------------------------------------------------
// Host orchestration
// Inputs (metadata order): hidden_states, cos, sin, wq, wk, wv, wo
// ---------------------------------------------------------------------------
extern "C" void kernel_launch(void* const* d_in, const int* in_sizes, int n_in,
                              void* d_out, int out_size)
{
    const float* hs   = (const float*)d_in[0];
    const float* cosT = (const float*)d_in[1];
    const float* sinT = (const float*)d_in[2];
    const float* wq   = (const float*)d_in[3];
    const float* wk   = (const float*)d_in[4];
    const float* wv   = (const float*)d_in[5];
    const float* wo   = (const float*)d_in[6];
    float* out = (float*)d_out;

    uint32_t *q, *k, *v, *attn, *hsT, *wqT, *wkT, *wvT, *woT;
    cudaGetSymbolAddress((void**)&q,    g_q);
    cudaGetSymbolAddress((void**)&k,    g_k);
    cudaGetSymbolAddress((void**)&v,    g_v);
    cudaGetSymbolAddress((void**)&attn, g_attn);
    cudaGetSymbolAddress((void**)&hsT,  g_hsT);
    cudaGetSymbolAddress((void**)&wqT,  g_wqT);
    cudaGetSymbolAddress((void**)&wkT,  g_wkT);
    cudaGetSymbolAddress((void**)&wvT,  g_wvT);
    cudaGetSymbolAddress((void**)&woT,  g_woT);

    cudaFuncSetAttribute(tf32_gemm_db, cudaFuncAttributeMaxDynamicSharedMemorySize,
                         GEMM_SMEM_BYTES);
    cudaFuncSetAttribute(flash_mma_kernel, cudaFuncAttributeMaxDynamicSharedMemorySize,
                         FLASH_SMEM_BYTES);

    // Pre-convert fp32 -> tf32 (row-major preserved)
    {
        const int T = 256;
        int n;
        n = S_LEN * HDIM / 4;
        cvt_tf32_kernel<<<(n + T - 1) / T, T>>>((const float4*)hs, (uint4*)hsT, n);
        n = HDIM * NQ * HD / 4;
        cvt_tf32_kernel<<<(n + T - 1) / T, T>>>((const float4*)wq, (uint4*)wqT, n);
        n = HDIM * NKV * HD / 4;
        cvt_tf32_kernel<<<(n + T - 1) / T, T>>>((const float4*)wk, (uint4*)wkT, n);
        cvt_tf32_kernel<<<(n + T - 1) / T, T>>>((const float4*)wv, (uint4*)wvT, n);
        n = NQ * HD * HDIM / 4;
        cvt_tf32_kernel<<<(n + T - 1) / T, T>>>((const float4*)wo, (uint4*)woT, n);
    }

    // Q projection (tf32-bit output): [2048,4096] @ [4096,4096]
    tf32_gemm_db<<<dim3(HDIM / 128, S_LEN / 128, 1), 256, GEMM_SMEM_BYTES>>>(
        hsT, wqT, wqT, (float*)q, (float*)q, S_LEN, NQ * HD, HDIM, 1);

    // K and V projections (tf32-bit output), fused via blockIdx.z
    tf32_gemm_db<<<dim3((NKV * HD) / 128, S_LEN / 128, 2), 256, GEMM_SMEM_BYTES>>>(
        hsT, wkT, wvT, (float*)k, (float*)v, S_LEN, NKV * HD, HDIM, 1);

    // RoPE in place (tf32 bits in/out); attention scale folded into Q
    rope_tf32_kernel<<<(S_LEN * NQ  * 64 + 255) / 256, 256>>>(
        q, cosT, sinT, NQ, 0.08838834764831845f);
    rope_tf32_kernel<<<(S_LEN * NKV * 64 + 255) / 256, 256>>>(
        k, cosT, sinT, NKV, 1.0f);

    // Flash attention (tf32 mma) -> attn holds tf32 bits
    flash_mma_kernel<<<dim3(NQ, S_LEN / 128), 256, FLASH_SMEM_BYTES>>>(
        q, k, v, attn);

    // Output projection: [2048,4096] @ [4096,4096] -> d_out (fp32)
    tf32_gemm_db<<<dim3(HDIM / 128, S_LEN / 128, 1), 256, GEMM_SMEM_BYTES>>>(
        attn, woT, woT, out, out, S_LEN, HDIM, NQ * HD, 0);
}